// round 4
// baseline (speedup 1.0000x reference)
#include <cuda_runtime.h>
#include <cuda_fp16.h>

#define BB 32
#define II 2048
#define JJ 64
#define MM 32
#define NN 16

// Scratch (device globals: allocation-free kernel_launch)
__device__ __half g_uhat_h[(size_t)BB * II * JJ * MM]; // 256 MB: [b][i][j][m] fp16
__device__ float  g_s[BB * JJ * MM];                   // routing accumulator
__device__ float  g_v[BB * JJ * MM];                   // v (then v0+v1)

// ---------------------------------------------------------------------------
__global__ void zero_s_kernel() {
    int i = blockIdx.x * 256 + threadIdx.x; // 256 x 256 = 65536 exact
    g_s[i] = 0.f;
}

// Packed f32x2 FMA: d = a*b + d (element-wise on {lo,hi})
__device__ __forceinline__ void fma2(unsigned long long& d,
                                     unsigned long long a,
                                     unsigned long long b) {
    asm("fma.rn.f32x2 %0, %1, %2, %0;" : "+l"(d) : "l"(a), "l"(b));
}

// ---------------------------------------------------------------------------
// Kernel 1: u_hat[b,i,j,m] = sum_n W[j,i,m,n] * x[b,i,n]  (fp32 f32x2 math,
// fp16 store, layout [b][i][j][m]). Fused: block-reduced sum_i into g_s.
// Block: (ib, j), 256 thr. Warp = i (8 concurrent), lane = (bq:8 -> 4b,
// mq:4 -> 8m). Accumulators n-paired in f32x2 (both operands reg-adjacent).
__global__ void __launch_bounds__(256, 2) uhat_kernel(const float* __restrict__ x,
                                                      const float* __restrict__ W) {
    __shared__ float smem_buf[8192]; // 32KB: x tile (16KB) in loop; red after
    float4* xs4 = (float4*)smem_buf;

    const int j     = blockIdx.y;
    const int ibase = blockIdx.x * 64;
    const int tid   = threadIdx.x;
    const int iw    = tid >> 5;     // warp -> i offset in tile
    const int tt    = tid & 31;
    const int bq    = tt >> 2;      // 0..7 -> b0 = 4*bq
    const int mq    = tt & 3;       // 0..3 -> m0 = 8*mq
    const int b0    = bq * 4;
    const int m0    = mq * 8;

    const float4* x4 = (const float4*)x;

    float sacc[32]; // [mm 0..7][bb 0..3]
#pragma unroll
    for (int e = 0; e < 32; e++) sacc[e] = 0.f;

    for (int tile = 0; tile < 8; ++tile) {
        const int i0 = ibase + tile * 8;
        // Stage x tile: 32b x 8i x 16n, slot-XOR by (b>>2) for conflict-free reads
#pragma unroll
        for (int k = 0; k < 4; k++) {
            int f = tid + k * 256;
            int bb2 = f >> 5, q = f & 31;
            xs4[bb2 * 32 + (q ^ (bb2 >> 2))] = x4[bb2 * 8192 + i0 * 4 + q];
        }
        __syncthreads();

        const int i = i0 + iw;
        const float* Wbase = W + ((size_t)j * 2048 + i) * 512; // 32m*16n

        unsigned long long acc[32]; // f32x2 n-paired, [mm][bb]
#pragma unroll
        for (int e = 0; e < 32; e++) acc[e] = 0ull;

#pragma unroll
        for (int nq = 0; nq < 4; nq++) {
            ulonglong2 xq[4];
            const int slot = (iw * 4 + nq) ^ bq;
#pragma unroll
            for (int bb = 0; bb < 4; bb++)
                xq[bb] = *(const ulonglong2*)&xs4[(b0 + bb) * 32 + slot];
#pragma unroll
            for (int mm = 0; mm < 8; mm++) {
                ulonglong2 wq = *(const ulonglong2*)(Wbase + (m0 + mm) * 16 + nq * 4);
#pragma unroll
                for (int bb = 0; bb < 4; bb++) {
                    fma2(acc[mm * 4 + bb], wq.x, xq[bb].x);
                    fma2(acc[mm * 4 + bb], wq.y, xq[bb].y);
                }
            }
        }

        // Collapse pairs, accumulate sacc, convert + store fp16 [b][i][j][m]
#pragma unroll
        for (int bb = 0; bb < 4; bb++) {
            float r[8];
#pragma unroll
            for (int mm = 0; mm < 8; mm++) {
                union { unsigned long long u; float2 f; } c;
                c.u = acc[mm * 4 + bb];
                float s = c.f.x + c.f.y;
                r[mm] = s;
                sacc[mm * 4 + bb] += s;
            }
            union { __half2 h[4]; uint4 u; } pk;
            pk.h[0] = __floats2half2_rn(r[0], r[1]);
            pk.h[1] = __floats2half2_rn(r[2], r[3]);
            pk.h[2] = __floats2half2_rn(r[4], r[5]);
            pk.h[3] = __floats2half2_rn(r[6], r[7]);
            *(uint4*)&g_uhat_h[(((size_t)(b0 + bb) * 2048 + i) * 64 + j) * 32 + m0] = pk.u;
        }
        __syncthreads(); // before next tile overwrites xs
    }

    // Block reduction of sacc across 8 warps (conflict-free XOR layout),
    // then 1024 atomics per block (instead of 8192).
    float* red = smem_buf;
#pragma unroll
    for (int e = 0; e < 32; e++)
        red[tt * 256 + iw * 32 + (e ^ tt)] = sacc[e];
    __syncthreads();
    {
        const int tt2 = tid >> 3;
        const int e0  = (tid & 7) * 4;
#pragma unroll
        for (int eo = 0; eo < 4; eo++) {
            int e = e0 + eo;
            float v = 0.f;
#pragma unroll
            for (int iw2 = 0; iw2 < 8; iw2++)
                v += red[tt2 * 256 + iw2 * 32 + (e ^ tt2)];
            int bb = (tt2 >> 2) * 4 + (e & 3);
            int mm = (tt2 & 3) * 8 + (e >> 2);
            atomicAdd(&g_s[(bb * 64 + j) * 32 + mm], v);
        }
    }
}

// ---------------------------------------------------------------------------
// Routing iteration: coalesced [b][i][j][m] stream, 8-i tiles, ping-pong cl,
// prefetch across barriers. Thread = (j = tid>>2, mg = tid&3) owns 8 m.
__global__ void __launch_bounds__(256) route_kernel() {
    __shared__ float cl[2][512];    // [buf][i(8)*64 + j]

    const int b     = blockIdx.y;
    const int ibase = blockIdx.x * 32;
    const int tid   = threadIdx.x;
    const int w     = tid >> 5;
    const int lane  = tid & 31;
    const int j     = tid >> 2;     // 0..63
    const int mg    = tid & 3;      // m-octet 0..3

    const uint4*  uh4 = (const uint4*)g_uhat_h;
    const float4* gv4 = (const float4*)g_v;

    const float4 vsA = gv4[b * 512 + j * 8 + mg * 2];
    const float4 vsB = gv4[b * 512 + j * 8 + mg * 2 + 1];

    // [b][i][j][m] fp16 -> uint4 idx = ((b*2048 + i)*64 + j)*4 + mg
    const uint4* __restrict__ ub = uh4 + (size_t)b * 524288 + j * 4 + mg;

    float sacc[8];
#pragma unroll
    for (int e = 0; e < 8; e++) sacc[e] = 0.f;

    uint4 cur[8], nxt[8];
#pragma unroll
    for (int iL = 0; iL < 8; iL++)
        cur[iL] = __ldg(&ub[(size_t)(ibase + iL) * 256]);

#pragma unroll
    for (int t = 0; t < 4; ++t) {
        // logits for 8 i
#pragma unroll
        for (int iL = 0; iL < 8; iL++) {
            union { uint4 u; __half2 h[4]; } uv; uv.u = cur[iL];
            float2 a0 = __half22float2(uv.h[0]);
            float2 a1 = __half22float2(uv.h[1]);
            float2 a2 = __half22float2(uv.h[2]);
            float2 a3 = __half22float2(uv.h[3]);
            float p = a0.x * vsA.x + a0.y * vsA.y + a1.x * vsA.z + a1.y * vsA.w +
                      a2.x * vsB.x + a2.y * vsB.y + a3.x * vsB.z + a3.y * vsB.w;
            p += __shfl_xor_sync(0xffffffffu, p, 1);
            p += __shfl_xor_sync(0xffffffffu, p, 2);
            if (mg == 0) cl[t & 1][iL * 64 + j] = p;
        }
        // prefetch next tile while barriers/softmax run
        if (t < 3) {
#pragma unroll
            for (int iL = 0; iL < 8; iL++)
                nxt[iL] = __ldg(&ub[(size_t)(ibase + (t + 1) * 8 + iL) * 256]);
        }
        __syncthreads();

        // softmax over j per i: warp w handles row i = w (2 j per lane)
        {
            float l0 = cl[t & 1][w * 64 + lane];
            float l1 = cl[t & 1][w * 64 + 32 + lane];
            float mx = fmaxf(l0, l1);
            mx = fmaxf(mx, __shfl_xor_sync(0xffffffffu, mx, 16));
            mx = fmaxf(mx, __shfl_xor_sync(0xffffffffu, mx, 8));
            mx = fmaxf(mx, __shfl_xor_sync(0xffffffffu, mx, 4));
            mx = fmaxf(mx, __shfl_xor_sync(0xffffffffu, mx, 2));
            mx = fmaxf(mx, __shfl_xor_sync(0xffffffffu, mx, 1));
            float e0 = __expf(l0 - mx), e1 = __expf(l1 - mx);
            float s = e0 + e1;
            s += __shfl_xor_sync(0xffffffffu, s, 16);
            s += __shfl_xor_sync(0xffffffffu, s, 8);
            s += __shfl_xor_sync(0xffffffffu, s, 4);
            s += __shfl_xor_sync(0xffffffffu, s, 2);
            s += __shfl_xor_sync(0xffffffffu, s, 1);
            float r = 1.f / s;
            cl[t & 1][w * 64 + lane]      = e0 * r;
            cl[t & 1][w * 64 + 32 + lane] = e1 * r;
        }
        __syncthreads();

        // c-weighted accumulation from the SAME registers
#pragma unroll
        for (int iL = 0; iL < 8; iL++) {
            float c = cl[t & 1][iL * 64 + j];
            union { uint4 u; __half2 h[4]; } uv; uv.u = cur[iL];
            float2 a0 = __half22float2(uv.h[0]);
            float2 a1 = __half22float2(uv.h[1]);
            float2 a2 = __half22float2(uv.h[2]);
            float2 a3 = __half22float2(uv.h[3]);
            sacc[0] += c * a0.x; sacc[1] += c * a0.y;
            sacc[2] += c * a1.x; sacc[3] += c * a1.y;
            sacc[4] += c * a2.x; sacc[5] += c * a2.y;
            sacc[6] += c * a3.x; sacc[7] += c * a3.y;
        }
        if (t < 3) {
#pragma unroll
            for (int iL = 0; iL < 8; iL++) cur[iL] = nxt[iL];
        }
    }

#pragma unroll
    for (int e = 0; e < 8; e++)
        atomicAdd(&g_s[(b * 64 + j) * 32 + mg * 8 + e], sacc[e]);
}

// ---------------------------------------------------------------------------
// v = squash(s*scale + bias). mode 0: g_v = v, zero s. mode 1: g_v += v,
// zero s. mode 2: write to dst (d_out).
__global__ void __launch_bounds__(256) squash_kernel(const float* __restrict__ bias,
                                                     float* __restrict__ dst,
                                                     float scale, int mode) {
    int idx = blockIdx.x * 256 + threadIdx.x; // 65536 exact
    int jm = idx & 2047;
    float sv = g_s[idx] * scale + bias[jm];
    float n2 = sv * sv; // lanes cover m=0..31 for one (b,j)
    n2 += __shfl_xor_sync(0xffffffffu, n2, 16);
    n2 += __shfl_xor_sync(0xffffffffu, n2, 8);
    n2 += __shfl_xor_sync(0xffffffffu, n2, 4);
    n2 += __shfl_xor_sync(0xffffffffu, n2, 2);
    n2 += __shfl_xor_sync(0xffffffffu, n2, 1);
    float vv = sv * n2 / ((1.f + n2) * sqrtf(n2 + 1e-8f));
    if (mode == 0)      { g_v[idx] = vv;  g_s[idx] = 0.f; }
    else if (mode == 1) { g_v[idx] += vv; g_s[idx] = 0.f; }
    else                { dst[idx] = vv; }
}

// ---------------------------------------------------------------------------
extern "C" void kernel_launch(void* const* d_in, const int* in_sizes, int n_in,
                              void* d_out, int out_size) {
    const float* x = nullptr;
    const float* W = nullptr;
    const float* bias = nullptr;
    for (int i = 0; i < n_in; i++) {
        if (in_sizes[i] == BB * II * NN)           x = (const float*)d_in[i];
        else if (in_sizes[i] == JJ * II * MM * NN) W = (const float*)d_in[i];
        else if (in_sizes[i] == JJ * MM)           bias = (const float*)d_in[i];
    }
    if (!x)    x    = (const float*)d_in[0];
    if (!W)    W    = (const float*)d_in[1];
    if (!bias) bias = (const float*)d_in[2];
    float* out = (float*)d_out;

    zero_s_kernel<<<256, 256>>>();
    dim3 g1(32, 64);
    uhat_kernel<<<g1, 256>>>(x, W);                         // u_hat + sum_i
    squash_kernel<<<256, 256>>>(bias, nullptr, 1.f / 64.f, 0); // v0
    dim3 g2(64, 32);
    route_kernel<<<g2, 256>>>();                            // iter 1 (vsum=v0)
    squash_kernel<<<256, 256>>>(bias, nullptr, 1.f, 1);     // v1, vsum=v0+v1
    route_kernel<<<g2, 256>>>();                            // iter 2
    squash_kernel<<<256, 256>>>(bias, out, 1.f, 2);         // v2 -> out
}

// round 5
// speedup vs baseline: 1.4084x; 1.4084x over previous
#include <cuda_runtime.h>
#include <cuda_fp16.h>

#define BB 32
#define II 2048
#define JJ 64
#define MM 32
#define NN 16

// Scratch (device globals: allocation-free kernel_launch)
__device__ __half g_uhat_h[(size_t)BB * JJ * II * MM]; // 256 MB: [b][j][i][m] fp16
__device__ float  g_s[BB * JJ * MM];                   // routing accumulator
__device__ float  g_v[BB * JJ * MM];                   // v (then v0+v1)

// ---------------------------------------------------------------------------
__global__ void zero_s_kernel() {
    int i = blockIdx.x * 256 + threadIdx.x; // 256 x 256 = 65536 exact
    g_s[i] = 0.f;
}

// ---------------------------------------------------------------------------
// Kernel 1 (round-3 proven version): u_hat[b,j,i,m] = sum_n W[j,i,m,n]*x[b,i,n]
// fp32 math, fp16 store. Also accumulates sum_i u_hat (fp32) into g_s.
__global__ void __launch_bounds__(256) uhat_kernel(const float* __restrict__ x,
                                                   const float* __restrict__ W) {
    __shared__ float4 ws4[1024]; // W tile: 8 i x 32 m x 16 n  (16 KB)
    __shared__ float4 xs4[1024]; // x tile: 32 b x 8 i x 16 n  (16 KB)

    const int j     = blockIdx.y;
    const int ibase = blockIdx.x * 64;
    const int tid   = threadIdx.x;
    const int g  = tid >> 6;      // i sub-group 0..3
    const int tt = tid & 63;
    const int bq = tt >> 3;       // 0..7 -> b0 = 4*bq
    const int mq = tt & 7;        // 0..7 -> m0 = 4*mq
    const int b0 = bq * 4;
    const int m0 = mq * 4;

    const float4* W4 = (const float4*)W;
    const float4* x4 = (const float4*)x;
    uint2*        u2 = (uint2*)g_uhat_h;

    float sacc[16];
#pragma unroll
    for (int e = 0; e < 16; e++) sacc[e] = 0.f;

    for (int tile = 0; tile < 8; ++tile) {
        const int i0 = ibase + tile * 8;
#pragma unroll
        for (int k = 0; k < 4; k++) {
            int f = tid + k * 256;
            float4 w = W4[(j * 2048 + i0) * 128 + f];
            int nq = f & 3, mrow = (f >> 2) & 31, iw = f >> 7;
            ws4[iw * 128 + mrow * 4 + (nq ^ ((mrow >> 2) & 3))] = w;
        }
#pragma unroll
        for (int k = 0; k < 4; k++) {
            int f = tid + k * 256;
            int bb = f >> 5, q = f & 31;
            int ii = q >> 2, nq = q & 3;
            xs4[bb * 32 + ii * 4 + (nq ^ ((bb >> 2) & 3))] = x4[bb * 8192 + i0 * 4 + q];
        }
        __syncthreads();

#pragma unroll
        for (int isub = 0; isub < 2; ++isub) {
            const int ii = isub * 4 + g;
            float acc[16];
#pragma unroll
            for (int e = 0; e < 16; e++) acc[e] = 0.f;

#pragma unroll
            for (int nq = 0; nq < 4; nq++) {
                float4 wr[4], xr[4];
#pragma unroll
                for (int m = 0; m < 4; m++)
                    wr[m] = ws4[ii * 128 + (m0 + m) * 4 + (nq ^ (mq & 3))];
#pragma unroll
                for (int b = 0; b < 4; b++)
                    xr[b] = xs4[(b0 + b) * 32 + ii * 4 + (nq ^ (bq & 3))];
#pragma unroll
                for (int b = 0; b < 4; b++)
#pragma unroll
                    for (int m = 0; m < 4; m++)
                        acc[b * 4 + m] += xr[b].x * wr[m].x + xr[b].y * wr[m].y +
                                          xr[b].z * wr[m].z + xr[b].w * wr[m].w;
            }
#pragma unroll
            for (int b = 0; b < 4; b++) {
                union { __half2 h[2]; uint2 u; } pk;
                pk.h[0] = __floats2half2_rn(acc[b * 4 + 0], acc[b * 4 + 1]);
                pk.h[1] = __floats2half2_rn(acc[b * 4 + 2], acc[b * 4 + 3]);
                u2[(size_t)(((b0 + b) * 64 + j) * 2048 + i0 + ii) * 8 + mq] = pk.u;
#pragma unroll
                for (int m = 0; m < 4; m++) sacc[b * 4 + m] += acc[b * 4 + m];
            }
        }
        __syncthreads();
    }

    float* red = (float*)ws4;
#pragma unroll
    for (int e = 0; e < 16; e++) red[tid * 16 + e] = sacc[e];
    __syncthreads();
    if (tid < 64) {
#pragma unroll
        for (int e = 0; e < 16; e++) {
            float v = red[tid * 16 + e] + red[(tid + 64) * 16 + e] +
                      red[(tid + 128) * 16 + e] + red[(tid + 192) * 16 + e];
            int b = e >> 2, m = e & 3;
            atomicAdd(&g_s[((b0 + b) * 64 + j) * 32 + m0 + m], v);
        }
    }
}

// ---------------------------------------------------------------------------
// Routing iteration (round-3 structure + cross-barrier prefetch).
// Thread = (j = tid>>2, mg = tid&3) owns m = mg*8..+7: one uint4 per i.
// Per 4-i tile: logits (2 shuffles/i) -> [prefetch next 4 loads] -> sync ->
// softmax -> sync -> accumulate from the SAME regs.
__global__ void __launch_bounds__(256, 3) route_kernel() {
    __shared__ float cl[256];       // logits -> coupling coeffs [i][j]

    const int b     = blockIdx.y;
    const int ibase = blockIdx.x * 32;
    const int tid   = threadIdx.x;
    const int w     = tid >> 5;
    const int lane  = tid & 31;
    const int j     = tid >> 2;     // 0..63
    const int mg    = tid & 3;      // m-octet 0..3

    const uint4*  uh4 = (const uint4*)g_uhat_h;
    const float4* gv4 = (const float4*)g_v;

    const float4 vsA = gv4[b * 512 + j * 8 + mg * 2];
    const float4 vsB = gv4[b * 512 + j * 8 + mg * 2 + 1];

    // [b][j][i][m] fp16 -> uint4 idx = ((b*64 + j)*2048 + i)*4 + mg
    const uint4* __restrict__ ub = uh4 + (size_t)(b * 64 + j) * 8192 + mg;

    float sacc[8];
#pragma unroll
    for (int e = 0; e < 8; e++) sacc[e] = 0.f;

    uint4 cur[4], nxt[4];
#pragma unroll
    for (int iL = 0; iL < 4; iL++)
        cur[iL] = __ldg(&ub[(ibase + iL) * 4]);

    for (int t = 0; t < 8; ++t) {
        // logits for 4 i from cur
        float p[4];
#pragma unroll
        for (int iL = 0; iL < 4; iL++) {
            union { uint4 u; __half2 h[4]; } uv; uv.u = cur[iL];
            float2 a0 = __half22float2(uv.h[0]);
            float2 a1 = __half22float2(uv.h[1]);
            float2 a2 = __half22float2(uv.h[2]);
            float2 a3 = __half22float2(uv.h[3]);
            p[iL] = a0.x * vsA.x + a0.y * vsA.y + a1.x * vsA.z + a1.y * vsA.w +
                    a2.x * vsB.x + a2.y * vsB.y + a3.x * vsB.z + a3.y * vsB.w;
            p[iL] += __shfl_xor_sync(0xffffffffu, p[iL], 1);
            p[iL] += __shfl_xor_sync(0xffffffffu, p[iL], 2);
        }
        if (mg == 0) {
#pragma unroll
            for (int iL = 0; iL < 4; iL++) cl[iL * 64 + j] = p[iL];
        }

        // prefetch next tile: in flight across both barriers + softmax
        if (t < 7) {
            const int i1 = ibase + (t + 1) * 4;
#pragma unroll
            for (int iL = 0; iL < 4; iL++)
                nxt[iL] = __ldg(&ub[(i1 + iL) * 4]);
        }
        __syncthreads();

        // softmax over j per i (warps 0..3; i = w, 2 j per lane)
        if (w < 4) {
            float l0 = cl[w * 64 + lane];
            float l1 = cl[w * 64 + 32 + lane];
            float mx = fmaxf(l0, l1);
            mx = fmaxf(mx, __shfl_xor_sync(0xffffffffu, mx, 16));
            mx = fmaxf(mx, __shfl_xor_sync(0xffffffffu, mx, 8));
            mx = fmaxf(mx, __shfl_xor_sync(0xffffffffu, mx, 4));
            mx = fmaxf(mx, __shfl_xor_sync(0xffffffffu, mx, 2));
            mx = fmaxf(mx, __shfl_xor_sync(0xffffffffu, mx, 1));
            float e0 = __expf(l0 - mx), e1 = __expf(l1 - mx);
            float s = e0 + e1;
            s += __shfl_xor_sync(0xffffffffu, s, 16);
            s += __shfl_xor_sync(0xffffffffu, s, 8);
            s += __shfl_xor_sync(0xffffffffu, s, 4);
            s += __shfl_xor_sync(0xffffffffu, s, 2);
            s += __shfl_xor_sync(0xffffffffu, s, 1);
            float r = 1.f / s;
            cl[w * 64 + lane]      = e0 * r;
            cl[w * 64 + 32 + lane] = e1 * r;
        }
        __syncthreads();

        // c-weighted accumulation from cur, then rotate in prefetched tile
#pragma unroll
        for (int iL = 0; iL < 4; iL++) {
            float c = cl[iL * 64 + j];
            union { uint4 u; __half2 h[4]; } uv; uv.u = cur[iL];
            float2 a0 = __half22float2(uv.h[0]);
            float2 a1 = __half22float2(uv.h[1]);
            float2 a2 = __half22float2(uv.h[2]);
            float2 a3 = __half22float2(uv.h[3]);
            sacc[0] += c * a0.x; sacc[1] += c * a0.y;
            sacc[2] += c * a1.x; sacc[3] += c * a1.y;
            sacc[4] += c * a2.x; sacc[5] += c * a2.y;
            sacc[6] += c * a3.x; sacc[7] += c * a3.y;
        }
#pragma unroll
        for (int iL = 0; iL < 4; iL++) cur[iL] = nxt[iL];
        __syncthreads(); // cl reused next tile
    }

#pragma unroll
    for (int e = 0; e < 8; e++)
        atomicAdd(&g_s[(b * 64 + j) * 32 + mg * 8 + e], sacc[e]);
}

// ---------------------------------------------------------------------------
// v = squash(s*scale + bias). mode 0: g_v = v, zero s. mode 1: g_v += v,
// zero s. mode 2: write to dst (d_out).
__global__ void __launch_bounds__(256) squash_kernel(const float* __restrict__ bias,
                                                     float* __restrict__ dst,
                                                     float scale, int mode) {
    int idx = blockIdx.x * 256 + threadIdx.x; // 65536 exact
    int jm = idx & 2047;
    float sv = g_s[idx] * scale + bias[jm];
    float n2 = sv * sv; // lanes cover m=0..31 for one (b,j)
    n2 += __shfl_xor_sync(0xffffffffu, n2, 16);
    n2 += __shfl_xor_sync(0xffffffffu, n2, 8);
    n2 += __shfl_xor_sync(0xffffffffu, n2, 4);
    n2 += __shfl_xor_sync(0xffffffffu, n2, 2);
    n2 += __shfl_xor_sync(0xffffffffu, n2, 1);
    float vv = sv * n2 / ((1.f + n2) * sqrtf(n2 + 1e-8f));
    if (mode == 0)      { g_v[idx] = vv;  g_s[idx] = 0.f; }
    else if (mode == 1) { g_v[idx] += vv; g_s[idx] = 0.f; }
    else                { dst[idx] = vv; }
}

// ---------------------------------------------------------------------------
extern "C" void kernel_launch(void* const* d_in, const int* in_sizes, int n_in,
                              void* d_out, int out_size) {
    const float* x = nullptr;
    const float* W = nullptr;
    const float* bias = nullptr;
    for (int i = 0; i < n_in; i++) {
        if (in_sizes[i] == BB * II * NN)           x = (const float*)d_in[i];
        else if (in_sizes[i] == JJ * II * MM * NN) W = (const float*)d_in[i];
        else if (in_sizes[i] == JJ * MM)           bias = (const float*)d_in[i];
    }
    if (!x)    x    = (const float*)d_in[0];
    if (!W)    W    = (const float*)d_in[1];
    if (!bias) bias = (const float*)d_in[2];
    float* out = (float*)d_out;

    zero_s_kernel<<<256, 256>>>();
    dim3 g1(32, 64);
    uhat_kernel<<<g1, 256>>>(x, W);                         // u_hat + sum_i
    squash_kernel<<<256, 256>>>(bias, nullptr, 1.f / 64.f, 0); // v0
    dim3 g2(64, 32);
    route_kernel<<<g2, 256>>>();                            // iter 1 (vsum=v0)
    squash_kernel<<<256, 256>>>(bias, nullptr, 1.f, 1);     // v1, vsum=v0+v1
    route_kernel<<<g2, 256>>>();                            // iter 2
    squash_kernel<<<256, 256>>>(bias, out, 1.f, 2);         // v2 -> out
}